// round 8
// baseline (speedup 1.0000x reference)
#include <cuda_runtime.h>
#include <cuda_fp16.h>
#include <cuda_bf16.h>
#include <cstdint>

#define OMEGA0 30.0f
#define FULLMASK 0xffffffffu
#define NWARPS 14

// SMEM layout (bytes):
//   [0, 65536)        : W3 b-fragments, fp16, frag-ordered: uint2 idx = k*256 + c*128 + t*32 + lane
//   [65536, +2048)    : W2 b-fragments bf16 HI : uint2 idx = (c*4+u)*32 + lane
//   [67584, +2048)    : W2 b-fragments bf16 LO
//   [69632, +128)     : W1 (32 f32)
#define W2F_HI    65536
#define W2F_LO    67584
#define W1S_OFF   69632
#define SMEM_BYTES (W1S_OFF + 128)

__device__ __forceinline__ void split_bf16(float2 p, uint32_t& hi, uint32_t& lo)
{
    __nv_bfloat162 h = __float22bfloat162_rn(p);
    float2 hf = __bfloat1622float2(h);
    __nv_bfloat162 l = __float22bfloat162_rn(make_float2(p.x - hf.x, p.y - hf.y));
    hi = *reinterpret_cast<uint32_t*>(&h);
    lo = *reinterpret_cast<uint32_t*>(&l);
}

__device__ __forceinline__ uint32_t to_h2(float2 p)
{
    __half2 h = __float22half2_rn(p);
    return *reinterpret_cast<uint32_t*>(&h);
}

__device__ __forceinline__ uint32_t f2h2u(float x)
{
    __half2 h = __float2half2_rn(x);
    return *reinterpret_cast<uint32_t*>(&h);
}

__device__ __forceinline__ uint32_t hmul2u(uint32_t a, uint32_t b)
{
    __half2 r = __hmul2(*reinterpret_cast<__half2*>(&a), *reinterpret_cast<__half2*>(&b));
    return *reinterpret_cast<uint32_t*>(&r);
}

__device__ __forceinline__ void red2(float* p, float x, float y)
{
    asm volatile("red.global.add.v2.f32 [%0], {%1, %2};" :: "l"(p), "f"(x), "f"(y) : "memory");
}

__device__ __forceinline__ void mma_bf16(float& d0, float& d1, float& d2, float& d3,
                                         uint32_t a0, uint32_t a1, uint32_t a2, uint32_t a3,
                                         uint32_t b0, uint32_t b1,
                                         float c0, float c1, float c2, float c3)
{
    asm volatile("mma.sync.aligned.m16n8k16.row.col.f32.bf16.bf16.f32 "
                 "{%0,%1,%2,%3}, {%4,%5,%6,%7}, {%8,%9}, {%10,%11,%12,%13};"
                 : "=f"(d0), "=f"(d1), "=f"(d2), "=f"(d3)
                 : "r"(a0), "r"(a1), "r"(a2), "r"(a3), "r"(b0), "r"(b1),
                   "f"(c0), "f"(c1), "f"(c2), "f"(c3));
}

__device__ __forceinline__ void mma_f16(float& d0, float& d1, float& d2, float& d3,
                                        uint32_t a0, uint32_t a1, uint32_t a2, uint32_t a3,
                                        uint32_t b0, uint32_t b1,
                                        float c0, float c1, float c2, float c3)
{
    asm volatile("mma.sync.aligned.m16n8k16.row.col.f32.f16.f16.f32 "
                 "{%0,%1,%2,%3}, {%4,%5,%6,%7}, {%8,%9}, {%10,%11,%12,%13};"
                 : "=f"(d0), "=f"(d1), "=f"(d2), "=f"(d3)
                 : "r"(a0), "r"(a1), "r"(a2), "r"(a3), "r"(b0), "r"(b1),
                   "f"(c0), "f"(c1), "f"(c2), "f"(c3));
}

__global__ __launch_bounds__(32 * NWARPS, 1)
void ckconv_side_kernel(const float* __restrict__ emb,     // [N, 32]
                        const float* __restrict__ t_node,  // [N]
                        const float* __restrict__ edges_t, // [E]
                        const int*   __restrict__ gidx,    // [E]
                        const int*   __restrict__ sidx,    // [E]
                        const float* __restrict__ W1,      // [32]
                        const float* __restrict__ W2,      // [32,32]
                        const float* __restrict__ W3,      // [32,1024]
                        float*       __restrict__ out,     // [Nseg, 32]
                        int E)
{
    extern __shared__ char smem_raw[];
    float* W1s = reinterpret_cast<float*>(smem_raw + W1S_OFF);

    const int tid  = threadIdx.x;
    const int lane = tid & 31;
    const int warp = tid >> 5;
    const int nthreads = 32 * NWARPS;

    // ---- Prologue: stage W3 as fp16 b-fragments ----
    {
        const float2* w3p = reinterpret_cast<const float2*>(W3);
        for (int id = tid; id < 8192; id += nthreads) {
            const int i = id & 31;
            const int t = (id >> 5) & 3;
            const int c = (id >> 7) & 1;
            const int k = id >> 8;
            const int hp = i >> 2;
            const int q  = i & 3;
            const size_t b2 = (size_t)k * 512 + (8 * t + hp) * 16 + 8 * c + q;
            const uint32_t b0 = to_h2(w3p[b2]);       // B rows 2q,2q+1
            const uint32_t b1 = to_h2(w3p[b2 + 4]);   // B rows 8+2q,9+2q
            reinterpret_cast<uint2*>(smem_raw)[(size_t)k * 256 + c * 128 + t * 32 + i] =
                make_uint2(b0, b1);
        }
        // W2 fragments, bf16 hi/lo
        for (int s = tid; s < 256; s += nthreads) {
            const int i = s & 31;
            const int u = (s >> 5) & 3;
            const int c = s >> 7;
            const int hp = i >> 2;
            const int q  = i & 3;
            const int n  = 8 * u + hp;
            const float x0 = W2[(16 * c + 2 * q) * 32 + n];
            const float x1 = W2[(16 * c + 2 * q + 1) * 32 + n];
            const float x2 = W2[(16 * c + 2 * q + 8) * 32 + n];
            const float x3 = W2[(16 * c + 2 * q + 9) * 32 + n];
            uint32_t h0, l0, h1, l1;
            split_bf16(make_float2(x0, x1), h0, l0);
            split_bf16(make_float2(x2, x3), h1, l1);
            reinterpret_cast<uint2*>(smem_raw + W2F_HI)[s] = make_uint2(h0, h1);
            reinterpret_cast<uint2*>(smem_raw + W2F_LO)[s] = make_uint2(l0, l1);
        }
        if (tid < 32) W1s[tid] = W1[tid];
    }
    __syncthreads();

    const int r0 = lane >> 2;        // fragment row group (rows r0 / r0+8)
    const int r1 = r0 + 8;
    const int q  = lane & 3;

    const int gwarp   = blockIdx.x * NWARPS + warp;
    const int nwarps  = gridDim.x * NWARPS;
    const int ngroups = (E + 31) >> 5;          // 32 edges per group
    const int njobs   = 2 * ngroups;            // x2 k-halves

    const float2* e2   = reinterpret_cast<const float2*>(emb);
    const float2* W1s2 = reinterpret_cast<const float2*>(W1s);
    const uint2*  w2hi = reinterpret_cast<const uint2*>(smem_raw + W2F_HI);
    const uint2*  w2lo = reinterpret_cast<const uint2*>(smem_raw + W2F_LO);
    const uint2*  w3f  = reinterpret_cast<const uint2*>(smem_raw);
    const float fz = 0.0f;

    #pragma unroll 1
    for (int j = gwarp; j < njobs; j += nwarps) {
        const int khalf = j & 1;                // this warp's 16-k half
        const int eb    = (j >> 1) << 5;        // 32-edge group base

        // ---- edge meta: lane carries edge eb+lane ----
        int el = eb + lane;
        if (el >= E) el = eb;                   // clamp tail (masked at scatter)
        const int   gl = gidx[el];
        const int   sl = sidx[el];
        const float tl = t_node[gl] - edges_t[el];

        // ---- layers 1-2 per 16-edge mtile: h2 for this warp's 2 u-groups ----
        float h2v[2][2][4];
        #pragma unroll
        for (int m = 0; m < 2; m++) {
            const float tA = __shfl_sync(FULLMASK, tl, 16 * m + r0);
            const float tB = __shfl_sync(FULLMASK, tl, 16 * m + r1);
            float s0[8], s1[8];
            #pragma unroll
            for (int jj = 0; jj < 4; jj++) {
                const float2 w1p = W1s2[4 * jj + q];
                s0[2 * jj]     = __sinf(OMEGA0 * tA * w1p.x);
                s0[2 * jj + 1] = __sinf(OMEGA0 * tA * w1p.y);
                s1[2 * jj]     = __sinf(OMEGA0 * tB * w1p.x);
                s1[2 * jj + 1] = __sinf(OMEGA0 * tB * w1p.y);
            }
            uint32_t Ah[2][4], Al[2][4];
            #pragma unroll
            for (int c = 0; c < 2; c++) {
                split_bf16(make_float2(s0[4 * c],     s0[4 * c + 1]), Ah[c][0], Al[c][0]);
                split_bf16(make_float2(s1[4 * c],     s1[4 * c + 1]), Ah[c][1], Al[c][1]);
                split_bf16(make_float2(s0[4 * c + 2], s0[4 * c + 3]), Ah[c][2], Al[c][2]);
                split_bf16(make_float2(s1[4 * c + 2], s1[4 * c + 3]), Ah[c][3], Al[c][3]);
            }
            float acc[2][4] = {{fz, fz, fz, fz}, {fz, fz, fz, fz}};
            #pragma unroll
            for (int c = 0; c < 2; c++) {
                #pragma unroll
                for (int up = 0; up < 2; up++) {
                    const int u = 2 * khalf + up;
                    const uint2 bh = w2hi[(c * 4 + u) * 32 + lane];
                    const uint2 bl = w2lo[(c * 4 + u) * 32 + lane];
                    mma_bf16(acc[up][0], acc[up][1], acc[up][2], acc[up][3],
                             Ah[c][0], Ah[c][1], Ah[c][2], Ah[c][3], bh.x, bh.y,
                             acc[up][0], acc[up][1], acc[up][2], acc[up][3]);
                    mma_bf16(acc[up][0], acc[up][1], acc[up][2], acc[up][3],
                             Al[c][0], Al[c][1], Al[c][2], Al[c][3], bh.x, bh.y,
                             acc[up][0], acc[up][1], acc[up][2], acc[up][3]);
                    mma_bf16(acc[up][0], acc[up][1], acc[up][2], acc[up][3],
                             Ah[c][0], Ah[c][1], Ah[c][2], Ah[c][3], bl.x, bl.y,
                             acc[up][0], acc[up][1], acc[up][2], acc[up][3]);
                }
            }
            #pragma unroll
            for (int up = 0; up < 2; up++)
                #pragma unroll
                for (int jj = 0; jj < 4; jj++)
                    h2v[m][up][jj] = __sinf(OMEGA0 * acc[up][jj]);
        }

        // ---- emb A-fragments, fp16, per mtile ----
        uint32_t Ae[2][2][4];
        #pragma unroll
        for (int m = 0; m < 2; m++) {
            const int gA = __shfl_sync(FULLMASK, gl, 16 * m + r0);
            const int gB = __shfl_sync(FULLMASK, gl, 16 * m + r1);
            #pragma unroll
            for (int c = 0; c < 2; c++) {
                Ae[m][c][0] = to_h2(e2[(size_t)gA * 16 + c * 8 + q]);
                Ae[m][c][1] = to_h2(e2[(size_t)gB * 16 + c * 8 + q]);
                Ae[m][c][2] = to_h2(e2[(size_t)gA * 16 + c * 8 + 4 + q]);
                Ae[m][c][3] = to_h2(e2[(size_t)gB * 16 + c * 8 + 4 + q]);
            }
        }

        // ---- main loop: this warp's 16 k-slices; mma accumulates msg directly ----
        float msg[2][4][4] = {};

        const int kbase = khalf << 4;
        #pragma unroll
        for (int k16 = 0; k16 < 16; k16++) {
            const int k    = kbase + k16;
            const int up   = k16 >> 3;
            const int b    = k16 & 1;
            const int qs   = (k16 & 7) >> 1;
            const int srcl = r0 * 4 + qs;

            uint32_t hA[2], hB[2];
            #pragma unroll
            for (int m = 0; m < 2; m++) {
                hA[m] = f2h2u(__shfl_sync(FULLMASK, h2v[m][up][b],     srcl));
                hB[m] = f2h2u(__shfl_sync(FULLMASK, h2v[m][up][2 + b], srcl));
            }
            // A = h2 (per-row) * emb
            uint32_t am[2][2][4];
            #pragma unroll
            for (int m = 0; m < 2; m++)
                #pragma unroll
                for (int c = 0; c < 2; c++) {
                    am[m][c][0] = hmul2u(hA[m], Ae[m][c][0]);
                    am[m][c][1] = hmul2u(hB[m], Ae[m][c][1]);
                    am[m][c][2] = hmul2u(hA[m], Ae[m][c][2]);
                    am[m][c][3] = hmul2u(hB[m], Ae[m][c][3]);
                }
            const uint2* bk = w3f + (size_t)k * 256;
            #pragma unroll
            for (int t = 0; t < 4; t++) {
                const uint2 b0 = bk[t * 32 + lane];        // c = 0
                const uint2 b1 = bk[128 + t * 32 + lane];  // c = 1
                #pragma unroll
                for (int m = 0; m < 2; m++) {
                    mma_f16(msg[m][t][0], msg[m][t][1], msg[m][t][2], msg[m][t][3],
                            am[m][0][0], am[m][0][1], am[m][0][2], am[m][0][3],
                            b0.x, b0.y,
                            msg[m][t][0], msg[m][t][1], msg[m][t][2], msg[m][t][3]);
                    mma_f16(msg[m][t][0], msg[m][t][1], msg[m][t][2], msg[m][t][3],
                            am[m][1][0], am[m][1][1], am[m][1][2], am[m][1][3],
                            b1.x, b1.y,
                            msg[m][t][0], msg[m][t][1], msg[m][t][2], msg[m][t][3]);
                }
            }
        }

        // ---- scatter (vectorized f32x2 reductions) ----
        #pragma unroll
        for (int m = 0; m < 2; m++) {
            const int  sA = __shfl_sync(FULLMASK, sl, 16 * m + r0);
            const int  sB = __shfl_sync(FULLMASK, sl, 16 * m + r1);
            const bool vA = (eb + 16 * m + r0) < E;
            const bool vB = (eb + 16 * m + r1) < E;
            #pragma unroll
            for (int t = 0; t < 4; t++) {
                const int h = t * 8 + 2 * q;
                if (vA) red2(out + (size_t)sA * 32 + h, msg[m][t][0], msg[m][t][1]);
                if (vB) red2(out + (size_t)sB * 32 + h, msg[m][t][2], msg[m][t][3]);
            }
        }
    }
}

extern "C" void kernel_launch(void* const* d_in, const int* in_sizes, int n_in,
                              void* d_out, int out_size)
{
    const float* u_emb   = (const float*)d_in[0];   // [U,32]
    const float* i_emb   = (const float*)d_in[1];   // [I,32]
    const int*   upt     = (const int*)  d_in[2];   // [E]
    const int*   ipt     = (const int*)  d_in[3];   // [E]
    const float* edges_t = (const float*)d_in[4];   // [E]
    const float* u_t     = (const float*)d_in[5];   // [U]
    const float* i_t     = (const float*)d_in[6];   // [I]
    const float* Wu1     = (const float*)d_in[7];
    const float* Wu2     = (const float*)d_in[8];
    const float* Wu3     = (const float*)d_in[9];
    const float* Wi1     = (const float*)d_in[10];
    const float* Wi2     = (const float*)d_in[11];
    const float* Wi3     = (const float*)d_in[12];

    const int E = in_sizes[4];
    const int U = in_sizes[5];

    float* out = (float*)d_out;

    cudaFuncSetAttribute(ckconv_side_kernel,
                         cudaFuncAttributeMaxDynamicSharedMemorySize, SMEM_BYTES);

    // Output is poisoned; segment-sum accumulates -> zero it first.
    cudaMemsetAsync(d_out, 0, (size_t)out_size * sizeof(float));

    const int grid = 148;
    const int threads = 32 * NWARPS;

    // hLu: item kernels applied to i_embedded[item], segment-summed by user index.
    ckconv_side_kernel<<<grid, threads, SMEM_BYTES>>>(
        i_emb, i_t, edges_t, ipt, upt, Wi1, Wi2, Wi3, out, E);

    // hLi: user kernels applied to u_embedded[user], summed by item index.
    ckconv_side_kernel<<<grid, threads, SMEM_BYTES>>>(
        u_emb, u_t, edges_t, upt, ipt, Wu1, Wu2, Wu3, out + (size_t)U * 32, E);
}

// round 9
// speedup vs baseline: 1.1261x; 1.1261x over previous
#include <cuda_runtime.h>
#include <cuda_fp16.h>
#include <cuda_bf16.h>
#include <cstdint>

#define OMEGA0 30.0f
#define FULLMASK 0xffffffffu
#define NWARPS 16

// SMEM layout (bytes):
//   [0, 65536)        : W3 b-fragments, fp16, k-PAIRED uint4:
//                       uint4 idx = kp*256 + c*128 + t*32 + lane,
//                       components = (b0 k=2kp, b1 k=2kp, b0 k=2kp+1, b1 k=2kp+1)
//   [65536, +2048)    : W2 b-fragments bf16 HI : uint2 idx = (c*4+u)*32 + lane
//   [67584, +2048)    : W2 b-fragments bf16 LO
//   [69632, +128)     : W1 (32 f32)
#define W2F_HI    65536
#define W2F_LO    67584
#define W1S_OFF   69632
#define SMEM_BYTES (W1S_OFF + 128)

__device__ __forceinline__ void split_bf16(float2 p, uint32_t& hi, uint32_t& lo)
{
    __nv_bfloat162 h = __float22bfloat162_rn(p);
    float2 hf = __bfloat1622float2(h);
    __nv_bfloat162 l = __float22bfloat162_rn(make_float2(p.x - hf.x, p.y - hf.y));
    hi = *reinterpret_cast<uint32_t*>(&h);
    lo = *reinterpret_cast<uint32_t*>(&l);
}

__device__ __forceinline__ uint32_t to_h2(float2 p)
{
    __half2 h = __float22half2_rn(p);
    return *reinterpret_cast<uint32_t*>(&h);
}

__device__ __forceinline__ uint32_t f2h2u(float x)
{
    __half2 h = __float2half2_rn(x);
    return *reinterpret_cast<uint32_t*>(&h);
}

__device__ __forceinline__ uint32_t hmul2u(uint32_t a, uint32_t b)
{
    __half2 r = __hmul2(*reinterpret_cast<__half2*>(&a), *reinterpret_cast<__half2*>(&b));
    return *reinterpret_cast<uint32_t*>(&r);
}

__device__ __forceinline__ void red2(float* p, float x, float y)
{
    asm volatile("red.global.add.v2.f32 [%0], {%1, %2};" :: "l"(p), "f"(x), "f"(y) : "memory");
}

__device__ __forceinline__ void mma_bf16(float& d0, float& d1, float& d2, float& d3,
                                         uint32_t a0, uint32_t a1, uint32_t a2, uint32_t a3,
                                         uint32_t b0, uint32_t b1,
                                         float c0, float c1, float c2, float c3)
{
    asm volatile("mma.sync.aligned.m16n8k16.row.col.f32.bf16.bf16.f32 "
                 "{%0,%1,%2,%3}, {%4,%5,%6,%7}, {%8,%9}, {%10,%11,%12,%13};"
                 : "=f"(d0), "=f"(d1), "=f"(d2), "=f"(d3)
                 : "r"(a0), "r"(a1), "r"(a2), "r"(a3), "r"(b0), "r"(b1),
                   "f"(c0), "f"(c1), "f"(c2), "f"(c3));
}

__device__ __forceinline__ void mma_f16(float& d0, float& d1, float& d2, float& d3,
                                        uint32_t a0, uint32_t a1, uint32_t a2, uint32_t a3,
                                        uint32_t b0, uint32_t b1,
                                        float c0, float c1, float c2, float c3)
{
    asm volatile("mma.sync.aligned.m16n8k16.row.col.f32.f16.f16.f32 "
                 "{%0,%1,%2,%3}, {%4,%5,%6,%7}, {%8,%9}, {%10,%11,%12,%13};"
                 : "=f"(d0), "=f"(d1), "=f"(d2), "=f"(d3)
                 : "r"(a0), "r"(a1), "r"(a2), "r"(a3), "r"(b0), "r"(b1),
                   "f"(c0), "f"(c1), "f"(c2), "f"(c3));
}

__global__ __launch_bounds__(32 * NWARPS, 1)
void ckconv_side_kernel(const float* __restrict__ emb,     // [N, 32]
                        const float* __restrict__ t_node,  // [N]
                        const float* __restrict__ edges_t, // [E]
                        const int*   __restrict__ gidx,    // [E]
                        const int*   __restrict__ sidx,    // [E]
                        const float* __restrict__ W1,      // [32]
                        const float* __restrict__ W2,      // [32,32]
                        const float* __restrict__ W3,      // [32,1024]
                        float*       __restrict__ out,     // [Nseg, 32]
                        int E)
{
    extern __shared__ char smem_raw[];
    float* W1s = reinterpret_cast<float*>(smem_raw + W1S_OFF);

    const int tid  = threadIdx.x;
    const int lane = tid & 31;
    const int warp = tid >> 5;
    const int nthreads = 32 * NWARPS;

    // ---- Prologue: stage W3 as k-paired fp16 b-fragments (uint4) ----
    {
        const float2* w3p = reinterpret_cast<const float2*>(W3);
        for (int id = tid; id < 4096; id += nthreads) {
            const int i  = id & 31;
            const int t  = (id >> 5) & 3;
            const int c  = (id >> 7) & 1;
            const int kp = id >> 8;             // 0..15
            const int hp = i >> 2;
            const int q  = i & 3;
            const int ke = 2 * kp;
            const size_t be = (size_t)ke * 512 + (8 * t + hp) * 16 + 8 * c + q;
            const size_t bo = be + 512;         // k odd
            uint4 v;
            v.x = to_h2(w3p[be]);               // even k: B rows 2q,2q+1
            v.y = to_h2(w3p[be + 4]);           // even k: B rows 8+2q,9+2q
            v.z = to_h2(w3p[bo]);               // odd k
            v.w = to_h2(w3p[bo + 4]);
            reinterpret_cast<uint4*>(smem_raw)[(size_t)kp * 256 + c * 128 + t * 32 + i] = v;
        }
        // W2 fragments, bf16 hi/lo
        for (int s = tid; s < 256; s += nthreads) {
            const int i = s & 31;
            const int u = (s >> 5) & 3;
            const int c = s >> 7;
            const int hp = i >> 2;
            const int q  = i & 3;
            const int n  = 8 * u + hp;
            const float x0 = W2[(16 * c + 2 * q) * 32 + n];
            const float x1 = W2[(16 * c + 2 * q + 1) * 32 + n];
            const float x2 = W2[(16 * c + 2 * q + 8) * 32 + n];
            const float x3 = W2[(16 * c + 2 * q + 9) * 32 + n];
            uint32_t h0, l0, h1, l1;
            split_bf16(make_float2(x0, x1), h0, l0);
            split_bf16(make_float2(x2, x3), h1, l1);
            reinterpret_cast<uint2*>(smem_raw + W2F_HI)[s] = make_uint2(h0, h1);
            reinterpret_cast<uint2*>(smem_raw + W2F_LO)[s] = make_uint2(l0, l1);
        }
        if (tid < 32) W1s[tid] = W1[tid];
    }
    __syncthreads();

    const int r0 = lane >> 2;        // fragment row group (rows r0 / r0+8)
    const int r1 = r0 + 8;
    const int q  = lane & 3;

    const int gwarp   = blockIdx.x * NWARPS + warp;
    const int nwarps  = gridDim.x * NWARPS;
    const int ngroups = (E + 31) >> 5;          // 32 edges per group
    const int njobs   = 2 * ngroups;            // x2 k-halves

    const float2* e2   = reinterpret_cast<const float2*>(emb);
    const float2* W1s2 = reinterpret_cast<const float2*>(W1s);
    const uint2*  w2hi = reinterpret_cast<const uint2*>(smem_raw + W2F_HI);
    const uint2*  w2lo = reinterpret_cast<const uint2*>(smem_raw + W2F_LO);
    const uint4*  w3f  = reinterpret_cast<const uint4*>(smem_raw);
    const float fz = 0.0f;

    #pragma unroll 1
    for (int j = gwarp; j < njobs; j += nwarps) {
        const int khalf = j & 1;                // this warp's 16-k half
        const int eb    = (j >> 1) << 5;        // 32-edge group base

        // ---- edge meta: lane carries edge eb+lane ----
        int el = eb + lane;
        if (el >= E) el = eb;                   // clamp tail (masked at scatter)
        const int   gl = gidx[el];
        const int   sl = sidx[el];
        const float tl = t_node[gl] - edges_t[el];

        // ---- layers 1-2 per 16-edge mtile: h2 (packed half2) for 2 u-groups ----
        uint32_t h2h[2][2][4];                  // [m][up][jj], packed (h2,h2) fp16
        #pragma unroll
        for (int m = 0; m < 2; m++) {
            const float tA = __shfl_sync(FULLMASK, tl, 16 * m + r0);
            const float tB = __shfl_sync(FULLMASK, tl, 16 * m + r1);
            float s0[8], s1[8];
            #pragma unroll
            for (int jj = 0; jj < 4; jj++) {
                const float2 w1p = W1s2[4 * jj + q];
                s0[2 * jj]     = __sinf(OMEGA0 * tA * w1p.x);
                s0[2 * jj + 1] = __sinf(OMEGA0 * tA * w1p.y);
                s1[2 * jj]     = __sinf(OMEGA0 * tB * w1p.x);
                s1[2 * jj + 1] = __sinf(OMEGA0 * tB * w1p.y);
            }
            uint32_t Ah[2][4], Al[2][4];
            #pragma unroll
            for (int c = 0; c < 2; c++) {
                split_bf16(make_float2(s0[4 * c],     s0[4 * c + 1]), Ah[c][0], Al[c][0]);
                split_bf16(make_float2(s1[4 * c],     s1[4 * c + 1]), Ah[c][1], Al[c][1]);
                split_bf16(make_float2(s0[4 * c + 2], s0[4 * c + 3]), Ah[c][2], Al[c][2]);
                split_bf16(make_float2(s1[4 * c + 2], s1[4 * c + 3]), Ah[c][3], Al[c][3]);
            }
            float acc[2][4] = {{fz, fz, fz, fz}, {fz, fz, fz, fz}};
            #pragma unroll
            for (int c = 0; c < 2; c++) {
                #pragma unroll
                for (int up = 0; up < 2; up++) {
                    const int u = 2 * khalf + up;
                    const uint2 bh = w2hi[(c * 4 + u) * 32 + lane];
                    const uint2 bl = w2lo[(c * 4 + u) * 32 + lane];
                    mma_bf16(acc[up][0], acc[up][1], acc[up][2], acc[up][3],
                             Ah[c][0], Ah[c][1], Ah[c][2], Ah[c][3], bh.x, bh.y,
                             acc[up][0], acc[up][1], acc[up][2], acc[up][3]);
                    mma_bf16(acc[up][0], acc[up][1], acc[up][2], acc[up][3],
                             Al[c][0], Al[c][1], Al[c][2], Al[c][3], bh.x, bh.y,
                             acc[up][0], acc[up][1], acc[up][2], acc[up][3]);
                    mma_bf16(acc[up][0], acc[up][1], acc[up][2], acc[up][3],
                             Ah[c][0], Ah[c][1], Ah[c][2], Ah[c][3], bl.x, bl.y,
                             acc[up][0], acc[up][1], acc[up][2], acc[up][3]);
                }
            }
            #pragma unroll
            for (int up = 0; up < 2; up++)
                #pragma unroll
                for (int jj = 0; jj < 4; jj++)
                    h2h[m][up][jj] = f2h2u(__sinf(OMEGA0 * acc[up][jj]));
        }

        // ---- emb A-fragments, fp16, per mtile ----
        uint32_t Ae[2][2][4];
        #pragma unroll
        for (int m = 0; m < 2; m++) {
            const int gA = __shfl_sync(FULLMASK, gl, 16 * m + r0);
            const int gB = __shfl_sync(FULLMASK, gl, 16 * m + r1);
            #pragma unroll
            for (int c = 0; c < 2; c++) {
                Ae[m][c][0] = to_h2(e2[(size_t)gA * 16 + c * 8 + q]);
                Ae[m][c][1] = to_h2(e2[(size_t)gB * 16 + c * 8 + q]);
                Ae[m][c][2] = to_h2(e2[(size_t)gA * 16 + c * 8 + 4 + q]);
                Ae[m][c][3] = to_h2(e2[(size_t)gB * 16 + c * 8 + 4 + q]);
            }
        }

        // ---- main loop: 8 k-pairs; one LDS.128 feeds both k's of a pair ----
        float msg[2][4][4] = {};

        const int kpbase = khalf << 3;          // pair index base
        #pragma unroll
        for (int kpi = 0; kpi < 8; kpi++) {
            const int up   = kpi >> 2;
            const int qs   = kpi & 3;
            const int srcl = r0 * 4 + qs;

            // packed h2 broadcast: even k -> jj 0/2, odd k -> jj 1/3
            uint32_t hAe[2], hBe[2], hAo[2], hBo[2];
            #pragma unroll
            for (int m = 0; m < 2; m++) {
                hAe[m] = __shfl_sync(FULLMASK, h2h[m][up][0], srcl);
                hBe[m] = __shfl_sync(FULLMASK, h2h[m][up][2], srcl);
                hAo[m] = __shfl_sync(FULLMASK, h2h[m][up][1], srcl);
                hBo[m] = __shfl_sync(FULLMASK, h2h[m][up][3], srcl);
            }

            const uint4* bk = w3f + (size_t)(kpbase + kpi) * 256;
            #pragma unroll
            for (int c = 0; c < 2; c++) {
                uint4 B[4];
                #pragma unroll
                for (int t = 0; t < 4; t++) B[t] = bk[c * 128 + t * 32 + lane];

                uint32_t amE[2][4], amO[2][4];
                #pragma unroll
                for (int m = 0; m < 2; m++) {
                    amE[m][0] = hmul2u(hAe[m], Ae[m][c][0]);
                    amE[m][1] = hmul2u(hBe[m], Ae[m][c][1]);
                    amE[m][2] = hmul2u(hAe[m], Ae[m][c][2]);
                    amE[m][3] = hmul2u(hBe[m], Ae[m][c][3]);
                    amO[m][0] = hmul2u(hAo[m], Ae[m][c][0]);
                    amO[m][1] = hmul2u(hBo[m], Ae[m][c][1]);
                    amO[m][2] = hmul2u(hAo[m], Ae[m][c][2]);
                    amO[m][3] = hmul2u(hBo[m], Ae[m][c][3]);
                }
                #pragma unroll
                for (int t = 0; t < 4; t++) {
                    #pragma unroll
                    for (int m = 0; m < 2; m++) {
                        mma_f16(msg[m][t][0], msg[m][t][1], msg[m][t][2], msg[m][t][3],
                                amE[m][0], amE[m][1], amE[m][2], amE[m][3],
                                B[t].x, B[t].y,
                                msg[m][t][0], msg[m][t][1], msg[m][t][2], msg[m][t][3]);
                        mma_f16(msg[m][t][0], msg[m][t][1], msg[m][t][2], msg[m][t][3],
                                amO[m][0], amO[m][1], amO[m][2], amO[m][3],
                                B[t].z, B[t].w,
                                msg[m][t][0], msg[m][t][1], msg[m][t][2], msg[m][t][3]);
                    }
                }
            }
        }

        // ---- scatter (vectorized f32x2 reductions) ----
        #pragma unroll
        for (int m = 0; m < 2; m++) {
            const int  sA = __shfl_sync(FULLMASK, sl, 16 * m + r0);
            const int  sB = __shfl_sync(FULLMASK, sl, 16 * m + r1);
            const bool vA = (eb + 16 * m + r0) < E;
            const bool vB = (eb + 16 * m + r1) < E;
            #pragma unroll
            for (int t = 0; t < 4; t++) {
                const int h = t * 8 + 2 * q;
                if (vA) red2(out + (size_t)sA * 32 + h, msg[m][t][0], msg[m][t][1]);
                if (vB) red2(out + (size_t)sB * 32 + h, msg[m][t][2], msg[m][t][3]);
            }
        }
    }
}

extern "C" void kernel_launch(void* const* d_in, const int* in_sizes, int n_in,
                              void* d_out, int out_size)
{
    const float* u_emb   = (const float*)d_in[0];   // [U,32]
    const float* i_emb   = (const float*)d_in[1];   // [I,32]
    const int*   upt     = (const int*)  d_in[2];   // [E]
    const int*   ipt     = (const int*)  d_in[3];   // [E]
    const float* edges_t = (const float*)d_in[4];   // [E]
    const float* u_t     = (const float*)d_in[5];   // [U]
    const float* i_t     = (const float*)d_in[6];   // [I]
    const float* Wu1     = (const float*)d_in[7];
    const float* Wu2     = (const float*)d_in[8];
    const float* Wu3     = (const float*)d_in[9];
    const float* Wi1     = (const float*)d_in[10];
    const float* Wi2     = (const float*)d_in[11];
    const float* Wi3     = (const float*)d_in[12];

    const int E = in_sizes[4];
    const int U = in_sizes[5];

    float* out = (float*)d_out;

    cudaFuncSetAttribute(ckconv_side_kernel,
                         cudaFuncAttributeMaxDynamicSharedMemorySize, SMEM_BYTES);

    // Output is poisoned; segment-sum accumulates -> zero it first.
    cudaMemsetAsync(d_out, 0, (size_t)out_size * sizeof(float));

    const int grid = 148;
    const int threads = 32 * NWARPS;

    // hLu: item kernels applied to i_embedded[item], segment-summed by user index.
    ckconv_side_kernel<<<grid, threads, SMEM_BYTES>>>(
        i_emb, i_t, edges_t, ipt, upt, Wi1, Wi2, Wi3, out, E);

    // hLi: user kernels applied to u_embedded[user], summed by item index.
    ckconv_side_kernel<<<grid, threads, SMEM_BYTES>>>(
        u_emb, u_t, edges_t, upt, ipt, Wu1, Wu2, Wu3, out + (size_t)U * 32, E);
}

// round 12
// speedup vs baseline: 1.1383x; 1.0108x over previous
#include <cuda_runtime.h>
#include <cuda_fp16.h>
#include <cuda_bf16.h>
#include <cstdint>

#define OMEGA0 30.0f
#define FULLMASK 0xffffffffu
#define NWARPS 16

// SMEM layout (bytes):
//   [0, 65536)        : W3 b-fragments, fp16, k-PAIRED uint4:
//                       uint4 idx = kp*256 + c*128 + t*32 + lane,
//                       components = (b0 k=2kp, b1 k=2kp, b0 k=2kp+1, b1 k=2kp+1)
//   [65536, +2048)    : W2 b-fragments bf16 HI : uint2 idx = (c*4+u)*32 + lane
//   [67584, +2048)    : W2 b-fragments bf16 LO
//   [69632, +128)     : W1 (32 f32)
#define W2F_HI    65536
#define W2F_LO    67584
#define W1S_OFF   69632
#define SMEM_BYTES (W1S_OFF + 128)

__device__ __forceinline__ void split_bf16(float2 p, uint32_t& hi, uint32_t& lo)
{
    __nv_bfloat162 h = __float22bfloat162_rn(p);
    float2 hf = __bfloat1622float2(h);
    __nv_bfloat162 l = __float22bfloat162_rn(make_float2(p.x - hf.x, p.y - hf.y));
    hi = *reinterpret_cast<uint32_t*>(&h);
    lo = *reinterpret_cast<uint32_t*>(&l);
}

__device__ __forceinline__ uint32_t to_h2(float2 p)
{
    __half2 h = __float22half2_rn(p);
    return *reinterpret_cast<uint32_t*>(&h);
}

__device__ __forceinline__ uint32_t f2h2u(float x)
{
    __half2 h = __float2half2_rn(x);
    return *reinterpret_cast<uint32_t*>(&h);
}

__device__ __forceinline__ uint32_t hmul2u(uint32_t a, uint32_t b)
{
    __half2 r = __hmul2(*reinterpret_cast<__half2*>(&a), *reinterpret_cast<__half2*>(&b));
    return *reinterpret_cast<uint32_t*>(&r);
}

__device__ __forceinline__ void red2(float* p, float x, float y)
{
    asm volatile("red.global.add.v2.f32 [%0], {%1, %2};" :: "l"(p), "f"(x), "f"(y) : "memory");
}

__device__ __forceinline__ void mma_bf16(float& d0, float& d1, float& d2, float& d3,
                                         uint32_t a0, uint32_t a1, uint32_t a2, uint32_t a3,
                                         uint32_t b0, uint32_t b1,
                                         float c0, float c1, float c2, float c3)
{
    asm volatile("mma.sync.aligned.m16n8k16.row.col.f32.bf16.bf16.f32 "
                 "{%0,%1,%2,%3}, {%4,%5,%6,%7}, {%8,%9}, {%10,%11,%12,%13};"
                 : "=f"(d0), "=f"(d1), "=f"(d2), "=f"(d3)
                 : "r"(a0), "r"(a1), "r"(a2), "r"(a3), "r"(b0), "r"(b1),
                   "f"(c0), "f"(c1), "f"(c2), "f"(c3));
}

__device__ __forceinline__ void mma_f16(float& d0, float& d1, float& d2, float& d3,
                                        uint32_t a0, uint32_t a1, uint32_t a2, uint32_t a3,
                                        uint32_t b0, uint32_t b1,
                                        float c0, float c1, float c2, float c3)
{
    asm volatile("mma.sync.aligned.m16n8k16.row.col.f32.f16.f16.f32 "
                 "{%0,%1,%2,%3}, {%4,%5,%6,%7}, {%8,%9}, {%10,%11,%12,%13};"
                 : "=f"(d0), "=f"(d1), "=f"(d2), "=f"(d3)
                 : "r"(a0), "r"(a1), "r"(a2), "r"(a3), "r"(b0), "r"(b1),
                   "f"(c0), "f"(c1), "f"(c2), "f"(c3));
}

__global__ __launch_bounds__(32 * NWARPS, 1)
void ckconv_side_kernel(const float* __restrict__ emb,     // [N, 32]
                        const float* __restrict__ t_node,  // [N]
                        const float* __restrict__ edges_t, // [E]
                        const int*   __restrict__ gidx,    // [E]
                        const int*   __restrict__ sidx,    // [E]
                        const float* __restrict__ W1,      // [32]
                        const float* __restrict__ W2,      // [32,32]
                        const float* __restrict__ W3,      // [32,1024]
                        float*       __restrict__ out,     // [Nseg, 32]
                        int E)
{
    extern __shared__ char smem_raw[];
    float* W1s = reinterpret_cast<float*>(smem_raw + W1S_OFF);

    const int tid  = threadIdx.x;
    const int lane = tid & 31;
    const int warp = tid >> 5;
    const int nthreads = 32 * NWARPS;

    // ---- Prologue: stage W3 as k-paired fp16 b-fragments (uint4) ----
    {
        const float2* w3p = reinterpret_cast<const float2*>(W3);
        for (int id = tid; id < 4096; id += nthreads) {
            const int i  = id & 31;
            const int t  = (id >> 5) & 3;
            const int c  = (id >> 7) & 1;
            const int kp = id >> 8;             // 0..15
            const int hp = i >> 2;
            const int q  = i & 3;
            const int ke = 2 * kp;
            const size_t be = (size_t)ke * 512 + (8 * t + hp) * 16 + 8 * c + q;
            const size_t bo = be + 512;         // k odd
            uint4 v;
            v.x = to_h2(w3p[be]);               // even k: B rows 2q,2q+1
            v.y = to_h2(w3p[be + 4]);           // even k: B rows 8+2q,9+2q
            v.z = to_h2(w3p[bo]);               // odd k
            v.w = to_h2(w3p[bo + 4]);
            reinterpret_cast<uint4*>(smem_raw)[(size_t)kp * 256 + c * 128 + t * 32 + i] = v;
        }
        // W2 fragments, bf16 hi/lo
        for (int s = tid; s < 256; s += nthreads) {
            const int i = s & 31;
            const int u = (s >> 5) & 3;
            const int c = s >> 7;
            const int hp = i >> 2;
            const int q  = i & 3;
            const int n  = 8 * u + hp;
            const float x0 = W2[(16 * c + 2 * q) * 32 + n];
            const float x1 = W2[(16 * c + 2 * q + 1) * 32 + n];
            const float x2 = W2[(16 * c + 2 * q + 8) * 32 + n];
            const float x3 = W2[(16 * c + 2 * q + 9) * 32 + n];
            uint32_t h0, l0, h1, l1;
            split_bf16(make_float2(x0, x1), h0, l0);
            split_bf16(make_float2(x2, x3), h1, l1);
            reinterpret_cast<uint2*>(smem_raw + W2F_HI)[s] = make_uint2(h0, h1);
            reinterpret_cast<uint2*>(smem_raw + W2F_LO)[s] = make_uint2(l0, l1);
        }
        if (tid < 32) W1s[tid] = W1[tid];
    }
    __syncthreads();

    const int r0 = lane >> 2;        // fragment row group (rows r0 / r0+8)
    const int r1 = r0 + 8;
    const int q  = lane & 3;

    const int gwarp   = blockIdx.x * NWARPS + warp;
    const int nwarps  = gridDim.x * NWARPS;
    const int ngroups = (E + 31) >> 5;          // 32 edges per group
    const int njobs   = 2 * ngroups;            // x2 k-halves

    const float2* e2   = reinterpret_cast<const float2*>(emb);
    const float2* W1s2 = reinterpret_cast<const float2*>(W1s);
    const uint2*  w2hi = reinterpret_cast<const uint2*>(smem_raw + W2F_HI);
    const uint2*  w2lo = reinterpret_cast<const uint2*>(smem_raw + W2F_LO);
    const uint4*  w3f  = reinterpret_cast<const uint4*>(smem_raw);
    const float fz = 0.0f;

    #pragma unroll 1
    for (int j = gwarp; j < njobs; j += nwarps) {
        const int khalf = j & 1;                // this warp's 16-k half
        const int eb    = (j >> 1) << 5;        // 32-edge group base

        // ---- edge meta: lane carries edge eb+lane ----
        int el = eb + lane;
        if (el >= E) el = eb;                   // clamp tail (masked at scatter)
        const int   gl = gidx[el];
        const int   sl = sidx[el];
        const float tl = t_node[gl] - edges_t[el];

        // ---- layers 1-2 per 16-edge mtile: h2 (packed half2) for 2 u-groups ----
        uint32_t h2h[2][2][4];                  // [m][up][jj], packed (h2,h2) fp16
        #pragma unroll
        for (int m = 0; m < 2; m++) {
            const float tA = __shfl_sync(FULLMASK, tl, 16 * m + r0);
            const float tB = __shfl_sync(FULLMASK, tl, 16 * m + r1);
            float s0[8], s1[8];
            #pragma unroll
            for (int jj = 0; jj < 4; jj++) {
                const float2 w1p = W1s2[4 * jj + q];
                s0[2 * jj]     = __sinf(OMEGA0 * tA * w1p.x);
                s0[2 * jj + 1] = __sinf(OMEGA0 * tA * w1p.y);
                s1[2 * jj]     = __sinf(OMEGA0 * tB * w1p.x);
                s1[2 * jj + 1] = __sinf(OMEGA0 * tB * w1p.y);
            }
            uint32_t Ah[2][4], Al[2][4];
            #pragma unroll
            for (int c = 0; c < 2; c++) {
                split_bf16(make_float2(s0[4 * c],     s0[4 * c + 1]), Ah[c][0], Al[c][0]);
                split_bf16(make_float2(s1[4 * c],     s1[4 * c + 1]), Ah[c][1], Al[c][1]);
                split_bf16(make_float2(s0[4 * c + 2], s0[4 * c + 3]), Ah[c][2], Al[c][2]);
                split_bf16(make_float2(s1[4 * c + 2], s1[4 * c + 3]), Ah[c][3], Al[c][3]);
            }
            float acc[2][4] = {{fz, fz, fz, fz}, {fz, fz, fz, fz}};
            #pragma unroll
            for (int c = 0; c < 2; c++) {
                #pragma unroll
                for (int up = 0; up < 2; up++) {
                    const int u = 2 * khalf + up;
                    const uint2 bh = w2hi[(c * 4 + u) * 32 + lane];
                    const uint2 bl = w2lo[(c * 4 + u) * 32 + lane];
                    mma_bf16(acc[up][0], acc[up][1], acc[up][2], acc[up][3],
                             Ah[c][0], Ah[c][1], Ah[c][2], Ah[c][3], bh.x, bh.y,
                             acc[up][0], acc[up][1], acc[up][2], acc[up][3]);
                    mma_bf16(acc[up][0], acc[up][1], acc[up][2], acc[up][3],
                             Al[c][0], Al[c][1], Al[c][2], Al[c][3], bh.x, bh.y,
                             acc[up][0], acc[up][1], acc[up][2], acc[up][3]);
                    mma_bf16(acc[up][0], acc[up][1], acc[up][2], acc[up][3],
                             Ah[c][0], Ah[c][1], Ah[c][2], Ah[c][3], bl.x, bl.y,
                             acc[up][0], acc[up][1], acc[up][2], acc[up][3]);
                }
            }
            #pragma unroll
            for (int up = 0; up < 2; up++)
                #pragma unroll
                for (int jj = 0; jj < 4; jj++)
                    h2h[m][up][jj] = f2h2u(__sinf(OMEGA0 * acc[up][jj]));
        }

        // ---- emb A-fragments, fp16, per mtile ----
        uint32_t Ae[2][2][4];
        #pragma unroll
        for (int m = 0; m < 2; m++) {
            const int gA = __shfl_sync(FULLMASK, gl, 16 * m + r0);
            const int gB = __shfl_sync(FULLMASK, gl, 16 * m + r1);
            #pragma unroll
            for (int c = 0; c < 2; c++) {
                Ae[m][c][0] = to_h2(e2[(size_t)gA * 16 + c * 8 + q]);
                Ae[m][c][1] = to_h2(e2[(size_t)gB * 16 + c * 8 + q]);
                Ae[m][c][2] = to_h2(e2[(size_t)gA * 16 + c * 8 + 4 + q]);
                Ae[m][c][3] = to_h2(e2[(size_t)gB * 16 + c * 8 + 4 + q]);
            }
        }

        // ---- main loop: 8 k-pairs; one LDS.128 feeds both k's of a pair.
        //      Issue ALL even-k mmas (8 chains) before the odd-k mmas so each
        //      accumulator is revisited at distance 8 mma (covers HMMA latency). ----
        float msg[2][4][4] = {};

        const int kpbase = khalf << 3;          // pair index base
        #pragma unroll
        for (int kpi = 0; kpi < 8; kpi++) {
            const int up   = kpi >> 2;
            const int qs   = kpi & 3;
            const int srcl = r0 * 4 + qs;

            // packed h2 broadcast: even k -> jj 0/2, odd k -> jj 1/3
            uint32_t hAe[2], hBe[2], hAo[2], hBo[2];
            #pragma unroll
            for (int m = 0; m < 2; m++) {
                hAe[m] = __shfl_sync(FULLMASK, h2h[m][up][0], srcl);
                hBe[m] = __shfl_sync(FULLMASK, h2h[m][up][2], srcl);
                hAo[m] = __shfl_sync(FULLMASK, h2h[m][up][1], srcl);
                hBo[m] = __shfl_sync(FULLMASK, h2h[m][up][3], srcl);
            }

            const uint4* bk = w3f + (size_t)(kpbase + kpi) * 256;
            #pragma unroll
            for (int c = 0; c < 2; c++) {
                uint4 B[4];
                #pragma unroll
                for (int t = 0; t < 4; t++) B[t] = bk[c * 128 + t * 32 + lane];

                uint32_t amE[2][4], amO[2][4];
                #pragma unroll
                for (int m = 0; m < 2; m++) {
                    amE[m][0] = hmul2u(hAe[m], Ae[m][c][0]);
                    amE[m][1] = hmul2u(hBe[m], Ae[m][c][1]);
                    amE[m][2] = hmul2u(hAe[m], Ae[m][c][2]);
                    amE[m][3] = hmul2u(hBe[m], Ae[m][c][3]);
                    amO[m][0] = hmul2u(hAo[m], Ae[m][c][0]);
                    amO[m][1] = hmul2u(hBo[m], Ae[m][c][1]);
                    amO[m][2] = hmul2u(hAo[m], Ae[m][c][2]);
                    amO[m][3] = hmul2u(hBo[m], Ae[m][c][3]);
                }
                // pass 1: even k — 8 independent accumulator chains
                #pragma unroll
                for (int t = 0; t < 4; t++)
                    #pragma unroll
                    for (int m = 0; m < 2; m++)
                        mma_f16(msg[m][t][0], msg[m][t][1], msg[m][t][2], msg[m][t][3],
                                amE[m][0], amE[m][1], amE[m][2], amE[m][3],
                                B[t].x, B[t].y,
                                msg[m][t][0], msg[m][t][1], msg[m][t][2], msg[m][t][3]);
                // pass 2: odd k — same chains, revisited at distance 8
                #pragma unroll
                for (int t = 0; t < 4; t++)
                    #pragma unroll
                    for (int m = 0; m < 2; m++)
                        mma_f16(msg[m][t][0], msg[m][t][1], msg[m][t][2], msg[m][t][3],
                                amO[m][0], amO[m][1], amO[m][2], amO[m][3],
                                B[t].z, B[t].w,
                                msg[m][t][0], msg[m][t][1], msg[m][t][2], msg[m][t][3]);
            }
        }

        // ---- scatter (vectorized f32x2 reductions) ----
        #pragma unroll
        for (int m = 0; m < 2; m++) {
            const int  sA = __shfl_sync(FULLMASK, sl, 16 * m + r0);
            const int  sB = __shfl_sync(FULLMASK, sl, 16 * m + r1);
            const bool vA = (eb + 16 * m + r0) < E;
            const bool vB = (eb + 16 * m + r1) < E;
            #pragma unroll
            for (int t = 0; t < 4; t++) {
                const int h = t * 8 + 2 * q;
                if (vA) red2(out + (size_t)sA * 32 + h, msg[m][t][0], msg[m][t][1]);
                if (vB) red2(out + (size_t)sB * 32 + h, msg[m][t][2], msg[m][t][3]);
            }
        }
    }
}

extern "C" void kernel_launch(void* const* d_in, const int* in_sizes, int n_in,
                              void* d_out, int out_size)
{
    const float* u_emb   = (const float*)d_in[0];   // [U,32]
    const float* i_emb   = (const float*)d_in[1];   // [I,32]
    const int*   upt     = (const int*)  d_in[2];   // [E]
    const int*   ipt     = (const int*)  d_in[3];   // [E]
    const float* edges_t = (const float*)d_in[4];   // [E]
    const float* u_t     = (const float*)d_in[5];   // [U]
    const float* i_t     = (const float*)d_in[6];   // [I]
    const float* Wu1     = (const float*)d_in[7];
    const float* Wu2     = (const float*)d_in[8];
    const float* Wu3     = (const float*)d_in[9];
    const float* Wi1     = (const float*)d_in[10];
    const float* Wi2     = (const float*)d_in[11];
    const float* Wi3     = (const float*)d_in[12];

    const int E = in_sizes[4];
    const int U = in_sizes[5];

    float* out = (float*)d_out;

    cudaFuncSetAttribute(ckconv_side_kernel,
                         cudaFuncAttributeMaxDynamicSharedMemorySize, SMEM_BYTES);

    // Output is poisoned; segment-sum accumulates -> zero it first.
    cudaMemsetAsync(d_out, 0, (size_t)out_size * sizeof(float));

    const int grid = 148;
    const int threads = 32 * NWARPS;

    // hLu: item kernels applied to i_embedded[item], segment-summed by user index.
    ckconv_side_kernel<<<grid, threads, SMEM_BYTES>>>(
        i_emb, i_t, edges_t, ipt, upt, Wi1, Wi2, Wi3, out, E);

    // hLi: user kernels applied to u_embedded[user], summed by item index.
    ckconv_side_kernel<<<grid, threads, SMEM_BYTES>>>(
        u_emb, u_t, edges_t, upt, ipt, Wu1, Wu2, Wu3, out + (size_t)U * 32, E);
}